// round 11
// baseline (speedup 1.0000x reference)
#include <cuda_runtime.h>
#include <cuda_bf16.h>
#include <cstdint>
#include <math.h>

// ---------------- problem dims ----------------
#define MROWS 8192
#define KDIM  9984
#define H1    1000
#define H1P   1024
#define H2    40

// ---------------- GEMM1 tiling ----------------
#define BM 128
#define BN 128
#define BK 64
#define STAGES 3
#define NKT (KDIM / BK)          // 156
#define KSPLIT 4
#define KT_PER (NKT / KSPLIT)    // 39
#define RSTRIDE 72               // bf16 elems per smem row (144 B) -> conflict-free ldmatrix
#define A_TILE_B (BM * RSTRIDE * 2)          // 18432
#define STAGE_B  ((BM + BN) * RSTRIDE * 2)   // 36864
#define SMEM_B   (STAGES * STAGE_B)          // 110592

// x-convert block split in fused convert kernel
#define W1_BLOCKS ((KDIM / 32) * (H1P / 32))   // 9984
#define X_BLOCKS  1024

// ---------------- scratch (device globals; no runtime alloc) ----------------
__device__ __nv_bfloat16 g_Xbf[(size_t)MROWS * KDIM];   // compact bf16 X rows
__device__ __nv_bfloat16 g_W1t[(size_t)H1P * KDIM];     // [n][k], rows >= 1000 zero
__device__ float g_psum[(size_t)KSPLIT * MROWS * H1P];  // split-K partials
__device__ float g_part[5][MROWS * H2];
__device__ float g_logits[MROWS];                       // compact
__device__ int   g_ts_is_i32;
__device__ unsigned char g_mark[MROWS];
__device__ int   g_cidx[MROWS];                         // (b,s) -> compact row
__device__ int   g_list[MROWS];                         // compact row -> original row
__device__ int   g_count, g_mtiles, g_ntiles, g_tile_ctr;

// ============================================================================
// helpers
// ============================================================================
__device__ __forceinline__ uint32_t smem_u32(const void* p) {
    uint32_t a;
    asm("{ .reg .u64 t; cvta.to.shared.u64 t, %1; cvt.u32.u64 %0, t; }"
        : "=r"(a) : "l"(p));
    return a;
}
__device__ __forceinline__ void cpa16(uint32_t dst, const void* src) {
    asm volatile("cp.async.cg.shared.global [%0], [%1], 16;\n" :: "r"(dst), "l"(src));
}
__device__ __forceinline__ void ldsm4(uint32_t& r0, uint32_t& r1, uint32_t& r2,
                                      uint32_t& r3, uint32_t addr) {
    asm volatile("ldmatrix.sync.aligned.m8n8.x4.shared.b16 {%0,%1,%2,%3}, [%4];"
                 : "=r"(r0), "=r"(r1), "=r"(r2), "=r"(r3) : "r"(addr));
}
__device__ __forceinline__ void mma_bf16(float* d, const uint32_t* a, const uint32_t* b) {
    asm volatile(
        "mma.sync.aligned.m16n8k16.row.col.f32.bf16.bf16.f32 "
        "{%0,%1,%2,%3}, {%4,%5,%6,%7}, {%8,%9}, {%0,%1,%2,%3};\n"
        : "+f"(d[0]), "+f"(d[1]), "+f"(d[2]), "+f"(d[3])
        : "r"(a[0]), "r"(a[1]), "r"(a[2]), "r"(a[3]), "r"(b[0]), "r"(b[1]));
}

// ============================================================================
// pre-chain: zero marks + dtype detect, scatter, scan/compact
// ============================================================================
__global__ void prep_kernel(const unsigned int* __restrict__ w) {
    if (blockIdx.x == 0) {
        ((unsigned long long*)g_mark)[threadIdx.x] = 0ULL;  // 1024 x 8B
    } else {
        __shared__ int s;
        if (threadIdx.x == 0) s = 0;
        __syncthreads();
        int loc = 0;
        for (int i = threadIdx.x; i < 4096; i += 1024)
            if (w[2 * i + 1] != 0u) loc = 1;
        if (loc) s = 1;
        __syncthreads();
        if (threadIdx.x == 0) g_ts_is_i32 = s;
    }
}

__global__ void scatter_mark_kernel(const void* __restrict__ tsp) {
    int i = blockIdx.x * 1024 + threadIdx.x;             // grid 8
    long long ts = g_ts_is_i32 ? (long long)((const int*)tsp)[i]
                               : ((const long long*)tsp)[i];
    if (ts != 0) g_mark[((i >> 9) << 9) + (int)ts] = 1;
}

__global__ void scan_kernel() {
    __shared__ int wsum[32];
    const int tid = threadIdx.x, lane = tid & 31, wid = tid >> 5;
    const int base = tid * 8;
    unsigned long long m = ((const unsigned long long*)g_mark)[tid];
    int bit[8], loc[8], s = 0;
#pragma unroll
    for (int j = 0; j < 8; j++) {
        bit[j] = (int)((m >> (8 * j)) & 1ULL);
        loc[j] = s;
        s += bit[j];
    }
    int v = s;
#pragma unroll
    for (int o = 1; o < 32; o <<= 1) {
        int u = __shfl_up_sync(0xffffffffu, v, o);
        if (lane >= o) v += u;
    }
    if (lane == 31) wsum[wid] = v;
    __syncthreads();
    if (wid == 0) {
        int w = wsum[lane];
#pragma unroll
        for (int o = 1; o < 32; o <<= 1) {
            int u = __shfl_up_sync(0xffffffffu, w, o);
            if (lane >= o) w += u;
        }
        wsum[lane] = w;
    }
    __syncthreads();
    int tb = (wid > 0 ? wsum[wid - 1] : 0) + (v - s);
#pragma unroll
    for (int j = 0; j < 8; j++) {
        if (bit[j]) {
            int c = tb + loc[j];
            g_cidx[base + j] = c;
            g_list[c] = base + j;
        }
    }
    int total = wsum[31];
    int mt = (total + 127) >> 7;
    if (tid == 0) {
        g_count = total;
        g_mtiles = mt;
        g_ntiles = mt * (H1P / BN) * KSPLIT;
        g_tile_ctr = 0;
    }
    for (int i = total + tid; i < mt * 128; i += 1024) g_list[i] = 0;  // pad
}

// ============================================================================
// fused converts: blocks [0, W1_BLOCKS) transpose W1; rest convert X rows
// ============================================================================
__global__ void convert_fused_kernel(const float* __restrict__ X,
                                     const float* __restrict__ W1) {
    if (blockIdx.x < W1_BLOCKS) {
        // --- W1[K][H1] fp32 -> g_W1t[H1P][K] bf16 (transpose + pad) ---
        __shared__ float t[32][33];
        const int tx = threadIdx.x & 31, ty = threadIdx.x >> 5;   // 32 x 8
        const int k0 = (blockIdx.x >> 5) * 32;     // 312 k-strips
        const int n0 = (blockIdx.x & 31) * 32;     // 32 n-strips
#pragma unroll
        for (int yy = 0; yy < 32; yy += 8) {
            int k = k0 + ty + yy, n = n0 + tx;
            t[ty + yy][tx] = (n < H1) ? W1[(size_t)k * H1 + n] : 0.0f;
        }
        __syncthreads();
#pragma unroll
        for (int yy = 0; yy < 32; yy += 8) {
            int n = n0 + ty + yy, k = k0 + tx;
            g_W1t[(size_t)n * KDIM + k] = __float2bfloat16(t[tx][ty + yy]);
        }
    } else {
        // --- compacted X rows fp32 -> bf16 ---
        const int padded = g_mtiles * 128;
        for (int r = blockIdx.x - W1_BLOCKS; r < padded; r += X_BLOCKS) {
            int row = g_list[r];
            const float4* src = (const float4*)(X + (size_t)row * KDIM);
            uint4* dst = (uint4*)(g_Xbf + (size_t)r * KDIM);
            for (int c = threadIdx.x; c < KDIM / 8; c += blockDim.x) {
                float4 v0 = src[2 * c], v1 = src[2 * c + 1];
                __nv_bfloat162 p0 = __floats2bfloat162_rn(v0.x, v0.y);
                __nv_bfloat162 p1 = __floats2bfloat162_rn(v0.z, v0.w);
                __nv_bfloat162 p2 = __floats2bfloat162_rn(v1.x, v1.y);
                __nv_bfloat162 p3 = __floats2bfloat162_rn(v1.z, v1.w);
                uint4 o;
                o.x = *(uint32_t*)&p0; o.y = *(uint32_t*)&p1;
                o.z = *(uint32_t*)&p2; o.w = *(uint32_t*)&p3;
                dst[c] = o;
            }
        }
    }
}

// ============================================================================
// GEMM1 (persistent, work-stealing, split-K=4): partials into g_psum
// BM=128 BN=128 BK=64, 8 warps (2m x 4n), warp tile 64x32, 2 CTAs/SM
// unit u: ks = u & 3 (K slice of 39 ktiles), t = u >> 2 -> (m0, n0)
// ============================================================================
__global__ void __launch_bounds__(256, 2)
gemm1_kernel() {
    extern __shared__ __align__(128) char smem[];
    const uint32_t sb = smem_u32(smem);
    __shared__ int s_t;

    const int tid = threadIdx.x;
    const int warp = tid >> 5;
    const int lane = tid & 31;
    const int warp_m = warp & 1;     // 0..1, 64 rows
    const int warp_n = warp >> 1;    // 0..3, 32 cols
    const int ntiles = g_ntiles;

    const uint32_t a_lane_row = (uint32_t)(lane & 15);
    const uint32_t a_lane_k   = (uint32_t)((lane >> 4) * 16);
    const int bj = lane >> 3;
    const uint32_t b_lane_row = (uint32_t)((bj >> 1) * 8 + (lane & 7));
    const uint32_t b_lane_k   = (uint32_t)((bj & 1) * 16);
    const int erow = lane >> 2;
    const int ecol = (lane & 3) * 2;

    while (true) {
        if (tid == 0) s_t = atomicAdd(&g_tile_ctr, 1);
        __syncthreads();
        const int u = s_t;
        if (u >= ntiles) break;
        const int ks = u & (KSPLIT - 1);
        const int t  = u >> 2;
        const int m0 = (t >> 3) * BM;      // H1P/BN = 8 n-tiles
        const int n0 = (t & 7) * BN;

        const __nv_bfloat16* Abase = g_Xbf + (size_t)m0 * KDIM + (size_t)ks * KT_PER * BK;
        const __nv_bfloat16* Bbase = g_W1t + (size_t)n0 * KDIM + (size_t)ks * KT_PER * BK;

        float acc[4][4][4];
#pragma unroll
        for (int i = 0; i < 4; i++)
#pragma unroll
            for (int j = 0; j < 4; j++)
#pragma unroll
                for (int r = 0; r < 4; r++) acc[i][j][r] = 0.0f;

        auto load_stage = [&](int kt, int stage) {
            uint32_t as = sb + stage * STAGE_B;
            uint32_t bs = as + A_TILE_B;
            const __nv_bfloat16* asrc = Abase + (size_t)kt * BK;
            const __nv_bfloat16* bsrc = Bbase + (size_t)kt * BK;
#pragma unroll
            for (int i = 0; i < 4; i++) {
                int c = tid + 256 * i;
                int r = c >> 3, q = c & 7;                  // 8 x 16B chunks per row
                cpa16(as + r * (RSTRIDE * 2) + q * 16, asrc + (size_t)r * KDIM + q * 8);
            }
#pragma unroll
            for (int i = 0; i < 4; i++) {
                int c = tid + 256 * i;
                int r = c >> 3, q = c & 7;
                cpa16(bs + r * (RSTRIDE * 2) + q * 16, bsrc + (size_t)r * KDIM + q * 8);
            }
        };

#pragma unroll
        for (int s = 0; s < STAGES - 1; s++) {
            load_stage(s, s);
            asm volatile("cp.async.commit_group;\n" ::);
        }

        int s_cmp = 0, s_fill = STAGES - 1;
        for (int kt = 0; kt < KT_PER; kt++) {
            asm volatile("cp.async.wait_group %0;\n" :: "n"(STAGES - 2));
            __syncthreads();
            if (kt + STAGES - 1 < KT_PER)
                load_stage(kt + STAGES - 1, s_fill);
            asm volatile("cp.async.commit_group;\n" ::);
            if (++s_fill == STAGES) s_fill = 0;

            const uint32_t as = sb + s_cmp * STAGE_B;
            const uint32_t bs = as + A_TILE_B;
            if (++s_cmp == STAGES) s_cmp = 0;

#pragma unroll
            for (int kss = 0; kss < 4; kss++) {
                uint32_t af[4][4];
#pragma unroll
                for (int ms = 0; ms < 4; ms++) {
                    uint32_t row = (uint32_t)(warp_m * 64 + ms * 16) + a_lane_row;
                    ldsm4(af[ms][0], af[ms][1], af[ms][2], af[ms][3],
                          as + row * (RSTRIDE * 2) + kss * 32 + a_lane_k);
                }
                uint32_t bf[4][2];
#pragma unroll
                for (int np = 0; np < 2; np++) {
                    uint32_t row = (uint32_t)(warp_n * 32 + np * 16) + b_lane_row;
                    ldsm4(bf[2 * np][0], bf[2 * np][1], bf[2 * np + 1][0], bf[2 * np + 1][1],
                          bs + row * (RSTRIDE * 2) + kss * 32 + b_lane_k);
                }
#pragma unroll
                for (int ms = 0; ms < 4; ms++)
#pragma unroll
                    for (int nf = 0; nf < 4; nf++)
                        mma_bf16(acc[ms][nf], af[ms], bf[nf]);
            }
        }

        // epilogue: raw partials -> g_psum[ks] (full 1024-wide, no predicates)
        float* pbase = g_psum + (size_t)ks * MROWS * H1P;
#pragma unroll
        for (int ms = 0; ms < 4; ms++) {
            int r0 = m0 + warp_m * 64 + ms * 16 + erow;
#pragma unroll
            for (int nf = 0; nf < 4; nf++) {
                int col = n0 + warp_n * 32 + nf * 8 + ecol;
                *(float2*)(pbase + (size_t)r0 * H1P + col) =
                    make_float2(acc[ms][nf][0], acc[ms][nf][1]);
                *(float2*)(pbase + (size_t)(r0 + 8) * H1P + col) =
                    make_float2(acc[ms][nf][2], acc[ms][nf][3]);
            }
        }
        asm volatile("cp.async.wait_group 0;\n" ::);
        __syncthreads();
    }
}

// ============================================================================
// head: GEMM2 k-split partials; reads psum slices directly (+bias+relu fused)
// grid (64, 5), block 128 (1 row/thread)
// ============================================================================
__global__ void head_partial_kernel(const float* __restrict__ W2,
                                    const float* __restrict__ b1) {
    if (blockIdx.x >= g_mtiles) return;
    __shared__ float hs[128][41];
    __shared__ float w2s[40 * 40];
    __shared__ float bls[40];
    const int tid = threadIdx.x;
    const int row0 = blockIdx.x * 128;
    const int kc0 = blockIdx.y * 5;

    const float* ps0 = g_psum + 0 * (size_t)MROWS * H1P;
    const float* ps1 = g_psum + 1 * (size_t)MROWS * H1P;
    const float* ps2 = g_psum + 2 * (size_t)MROWS * H1P;
    const float* ps3 = g_psum + 3 * (size_t)MROWS * H1P;

    float acc[H2];
#pragma unroll
    for (int c = 0; c < H2; c++) acc[c] = 0.0f;

    for (int kc = kc0; kc < kc0 + 5; kc++) {
        if (tid < 40) bls[tid] = b1[kc * 40 + tid];
#pragma unroll 8
        for (int i = 0; i < 40; i++) {
            int idx = tid + 128 * i;
            int r = idx / 40, k = idx - r * 40;
            size_t off = (size_t)(row0 + r) * H1P + kc * 40 + k;
            float v = ps0[off] + ps1[off] + ps2[off] + ps3[off];
            hs[r][k] = v;   // bias added after sync (needs bls)
        }
        __syncthreads();
#pragma unroll 8
        for (int i = 0; i < 40; i++) {
            int idx = tid + 128 * i;
            int r = idx / 40, k = idx - r * 40;
            hs[r][k] = fmaxf(hs[r][k] + bls[k], 0.0f);
        }
#pragma unroll
        for (int i = 0; i < 13; i++) {
            int idx = tid + 128 * i;
            if (idx < 1600) w2s[idx] = W2[kc * 40 * H2 + idx];
        }
        __syncthreads();
#pragma unroll 5
        for (int k = 0; k < 40; k++) {
            float a = hs[tid][k];
            const float4* wr = (const float4*)(w2s + k * H2);
#pragma unroll
            for (int c4 = 0; c4 < 10; c4++) {
                float4 w = wr[c4];
                acc[c4 * 4 + 0] += a * w.x;
                acc[c4 * 4 + 1] += a * w.y;
                acc[c4 * 4 + 2] += a * w.z;
                acc[c4 * 4 + 3] += a * w.w;
            }
        }
        __syncthreads();
    }
    float4* dst = (float4*)&g_part[blockIdx.y][(row0 + tid) * H2];
#pragma unroll
    for (int c4 = 0; c4 < 10; c4++)
        dst[c4] = make_float4(acc[c4 * 4], acc[c4 * 4 + 1], acc[c4 * 4 + 2], acc[c4 * 4 + 3]);
}

__global__ void head_combine_kernel(const float* __restrict__ b2,
                                    const float* __restrict__ W3,
                                    const float* __restrict__ b3) {
    int row = blockIdx.x * blockDim.x + threadIdx.x;
    if (row >= g_mtiles * 128) return;
    float4 a[10];
    const float4* p0 = (const float4*)&g_part[0][row * H2];
#pragma unroll
    for (int i = 0; i < 10; i++) a[i] = p0[i];
#pragma unroll
    for (int p = 1; p < 5; p++) {
        const float4* pp = (const float4*)&g_part[p][row * H2];
#pragma unroll
        for (int i = 0; i < 10; i++) {
            float4 v = pp[i];
            a[i].x += v.x; a[i].y += v.y; a[i].z += v.z; a[i].w += v.w;
        }
    }
    float logit = b3[0];
#pragma unroll
    for (int i = 0; i < 10; i++) {
        float4 bb = *(const float4*)(b2 + i * 4);
        float4 ww = *(const float4*)(W3 + i * 4);
        logit += fmaxf(a[i].x + bb.x, 0.0f) * ww.x;
        logit += fmaxf(a[i].y + bb.y, 0.0f) * ww.y;
        logit += fmaxf(a[i].z + bb.z, 0.0f) * ww.z;
        logit += fmaxf(a[i].w + bb.w, 0.0f) * ww.w;
    }
    g_logits[row] = 1.0f / (1.0f + expf(-logit));
}

// ============================================================================
// masked gather through the inverse map
// ============================================================================
__global__ void gather_kernel(const void* __restrict__ tsp, float* __restrict__ out) {
    int i = blockIdx.x * blockDim.x + threadIdx.x;
    if (i >= MROWS) return;
    long long ts = g_ts_is_i32 ? (long long)((const int*)tsp)[i]
                               : ((const long long*)tsp)[i];
    float r = 0.0f;
    if (ts != 0) {
        int pos = ((i >> 9) << 9) + (int)ts;
        r = g_logits[g_cidx[pos]];
    }
    out[i] = r;
}

// ============================================================================
// launch
// ============================================================================
extern "C" void kernel_launch(void* const* d_in, const int* in_sizes, int n_in,
                              void* d_out, int out_size) {
    const float* X   = (const float*)d_in[0];
    const void*  tsp = d_in[1];
    const float* W1  = (const float*)d_in[2];
    const float* b1  = (const float*)d_in[3];
    const float* W2  = (const float*)d_in[4];
    const float* b2  = (const float*)d_in[5];
    const float* W3  = (const float*)d_in[6];
    const float* b3  = (const float*)d_in[7];
    float* out = (float*)d_out;
    (void)in_sizes; (void)n_in; (void)out_size;

    cudaFuncSetAttribute(gemm1_kernel,
                         cudaFuncAttributeMaxDynamicSharedMemorySize, SMEM_B);

    prep_kernel<<<2, 1024>>>((const unsigned int*)tsp);
    scatter_mark_kernel<<<8, 1024>>>(tsp);
    scan_kernel<<<1, 1024>>>();

    convert_fused_kernel<<<W1_BLOCKS + X_BLOCKS, 256>>>(X, W1);

    gemm1_kernel<<<296, 256, SMEM_B>>>();

    head_partial_kernel<<<dim3(64, 5), 128>>>(W2, b1);
    head_combine_kernel<<<32, 256>>>(b2, W3, b3);
    gather_kernel<<<32, 256>>>(tsp, out);
}

// round 12
// speedup vs baseline: 1.0070x; 1.0070x over previous
#include <cuda_runtime.h>
#include <cuda_bf16.h>
#include <cstdint>
#include <math.h>

// ---------------- problem dims ----------------
#define MROWS 8192
#define KDIM  9984
#define H1    1000
#define H1P   1024
#define H2    40

// ---------------- GEMM1 tiling (R10-proven) ----------------
#define BM 128
#define BN 128
#define BK 32
#define STAGES 4
#define NKT (KDIM / BK)          // 312
#define KSPLIT 4
#define KT_PER (NKT / KSPLIT)    // 78
#define RSTRIDE 40               // bf16 elems per smem row (80 B) -> conflict-free ldmatrix
#define A_TILE_B (BM * RSTRIDE * 2)          // 10240
#define STAGE_B  ((BM + BN) * RSTRIDE * 2)   // 20480
#define SMEM_B   (STAGES * STAGE_B)          // 81920

// ---------------- scratch (device globals; no runtime alloc) ----------------
__device__ __nv_bfloat16 g_Xbf[(size_t)MROWS * KDIM];   // compact bf16 X rows
__device__ __nv_bfloat16 g_W1t[(size_t)H1P * KDIM];     // [n][k], rows >= 1000 zero
__device__ float g_psum[(size_t)KSPLIT * MROWS * H1P];  // split-K partials
__device__ float g_part[5][MROWS * H2];
__device__ float g_logits[MROWS];                       // compact
__device__ int   g_ts_is_i32;
__device__ int   g_cidx[MROWS];                         // (b,s) -> compact row
__device__ int   g_list[MROWS];                         // compact row -> original row
__device__ int   g_count, g_mtiles, g_ntiles, g_tile_ctr;

// ============================================================================
// helpers
// ============================================================================
__device__ __forceinline__ uint32_t smem_u32(const void* p) {
    uint32_t a;
    asm("{ .reg .u64 t; cvta.to.shared.u64 t, %1; cvt.u32.u64 %0, t; }"
        : "=r"(a) : "l"(p));
    return a;
}
__device__ __forceinline__ void cpa16(uint32_t dst, const void* src) {
    asm volatile("cp.async.cg.shared.global [%0], [%1], 16;\n" :: "r"(dst), "l"(src));
}
__device__ __forceinline__ void ldsm4(uint32_t& r0, uint32_t& r1, uint32_t& r2,
                                      uint32_t& r3, uint32_t addr) {
    asm volatile("ldmatrix.sync.aligned.m8n8.x4.shared.b16 {%0,%1,%2,%3}, [%4];"
                 : "=r"(r0), "=r"(r1), "=r"(r2), "=r"(r3) : "r"(addr));
}
__device__ __forceinline__ void mma_bf16(float* d, const uint32_t* a, const uint32_t* b) {
    asm volatile(
        "mma.sync.aligned.m16n8k16.row.col.f32.bf16.bf16.f32 "
        "{%0,%1,%2,%3}, {%4,%5,%6,%7}, {%8,%9}, {%0,%1,%2,%3};\n"
        : "+f"(d[0]), "+f"(d[1]), "+f"(d[2]), "+f"(d[3])
        : "r"(a[0]), "r"(a[1]), "r"(a[2]), "r"(a[3]), "r"(b[0]), "r"(b[1]));
}

// ============================================================================
// merged prep: detect dtype, mark (in smem), scan, compact -- ONE block
// ============================================================================
__global__ void prep_all_kernel(const void* __restrict__ tsp) {
    __shared__ unsigned char mark[MROWS];    // 8 KB
    __shared__ int wsum[32];
    __shared__ int s_is32;
    const int tid = threadIdx.x, lane = tid & 31, wid = tid >> 5;

    // --- phase 1: dtype detect (int64 => all odd u32 words zero) ---
    if (tid == 0) s_is32 = 0;
    __syncthreads();
    {
        const unsigned int* w = (const unsigned int*)tsp;
        int loc = 0;
#pragma unroll
        for (int j = 0; j < 4; j++)
            if (w[2 * (tid + 1024 * j) + 1] != 0u) loc = 1;
        if (loc) s_is32 = 1;
    }
    // --- phase 2: zero marks ---
    ((unsigned long long*)mark)[tid] = 0ULL;
    __syncthreads();
    const int is32 = s_is32;

    // --- phase 3: scatter marks ---
#pragma unroll
    for (int j = 0; j < 8; j++) {
        int i = tid + 1024 * j;
        long long ts = is32 ? (long long)((const int*)tsp)[i]
                            : ((const long long*)tsp)[i];
        if (ts != 0) mark[((i >> 9) << 9) + (int)ts] = 1;
    }
    __syncthreads();

    // --- phase 4: scan + compact ---
    const int base = tid * 8;
    unsigned long long m = ((const unsigned long long*)mark)[tid];
    int bit[8], loc8[8], s = 0;
#pragma unroll
    for (int j = 0; j < 8; j++) {
        bit[j] = (int)((m >> (8 * j)) & 1ULL);
        loc8[j] = s;
        s += bit[j];
    }
    int v = s;
#pragma unroll
    for (int o = 1; o < 32; o <<= 1) {
        int u = __shfl_up_sync(0xffffffffu, v, o);
        if (lane >= o) v += u;
    }
    if (lane == 31) wsum[wid] = v;
    __syncthreads();
    if (wid == 0) {
        int w = wsum[lane];
#pragma unroll
        for (int o = 1; o < 32; o <<= 1) {
            int u = __shfl_up_sync(0xffffffffu, w, o);
            if (lane >= o) w += u;
        }
        wsum[lane] = w;
    }
    __syncthreads();
    int tb = (wid > 0 ? wsum[wid - 1] : 0) + (v - s);
#pragma unroll
    for (int j = 0; j < 8; j++) {
        if (bit[j]) {
            int c = tb + loc8[j];
            g_cidx[base + j] = c;
            g_list[c] = base + j;
        }
    }
    const int total = wsum[31];
    const int mt = (total + 127) >> 7;
    if (tid == 0) {
        g_count = total;
        g_mtiles = mt;
        g_ntiles = mt * (H1P / BN) * KSPLIT;
        g_tile_ctr = 0;
    }
    __syncthreads();
    if (tid == 0) g_ts_is_i32 = is32;
    for (int i = total + tid; i < mt * 128; i += 1024) g_list[i] = 0;  // pad
}

// ============================================================================
// pre-pass: convert only needed X rows fp32 -> bf16 (compact layout)
// ============================================================================
__global__ void convert_x_rows_kernel(const float* __restrict__ X) {
    const int padded = g_mtiles * 128;
    for (int r = blockIdx.x; r < padded; r += gridDim.x) {
        int row = g_list[r];
        const float4* src = (const float4*)(X + (size_t)row * KDIM);
        uint4* dst = (uint4*)(g_Xbf + (size_t)r * KDIM);
        for (int c = threadIdx.x; c < KDIM / 8; c += blockDim.x) {
            float4 v0 = src[2 * c], v1 = src[2 * c + 1];
            __nv_bfloat162 p0 = __floats2bfloat162_rn(v0.x, v0.y);
            __nv_bfloat162 p1 = __floats2bfloat162_rn(v0.z, v0.w);
            __nv_bfloat162 p2 = __floats2bfloat162_rn(v1.x, v1.y);
            __nv_bfloat162 p3 = __floats2bfloat162_rn(v1.z, v1.w);
            uint4 o;
            o.x = *(uint32_t*)&p0; o.y = *(uint32_t*)&p1;
            o.z = *(uint32_t*)&p2; o.w = *(uint32_t*)&p3;
            dst[c] = o;
        }
    }
}

// W1[K][H1] fp32 -> g_W1t[H1P][K] bf16 (transpose + pad)
__global__ void convert_w1_kernel(const float* __restrict__ W1) {
    __shared__ float t[32][33];
    int k0 = blockIdx.x * 32, n0 = blockIdx.y * 32;
#pragma unroll
    for (int yy = 0; yy < 32; yy += 8) {
        int k = k0 + threadIdx.y + yy, n = n0 + threadIdx.x;
        t[threadIdx.y + yy][threadIdx.x] = (n < H1) ? W1[(size_t)k * H1 + n] : 0.0f;
    }
    __syncthreads();
#pragma unroll
    for (int yy = 0; yy < 32; yy += 8) {
        int n = n0 + threadIdx.y + yy, k = k0 + threadIdx.x;
        g_W1t[(size_t)n * KDIM + k] = __float2bfloat16(t[threadIdx.x][threadIdx.y + yy]);
    }
}

// ============================================================================
// GEMM1 (persistent, work-stealing, split-K=4): partials into g_psum
// BM=128 BN=128 BK=32, 8 warps (2m x 4n), warp tile 64x32, 2 CTAs/SM
// ============================================================================
__global__ void __launch_bounds__(256, 2)
gemm1_kernel() {
    extern __shared__ __align__(128) char smem[];
    const uint32_t sb = smem_u32(smem);
    __shared__ int s_t;

    const int tid = threadIdx.x;
    const int warp = tid >> 5;
    const int lane = tid & 31;
    const int warp_m = warp & 1;     // 0..1, 64 rows
    const int warp_n = warp >> 1;    // 0..3, 32 cols
    const int ntiles = g_ntiles;

    const int lr = tid >> 2;         // 0..63
    const int lc = tid & 3;          // 0..3
    const uint32_t a_lane_row = (uint32_t)(lane & 15);
    const uint32_t a_lane_k   = (uint32_t)((lane >> 4) * 16);
    const int bj = lane >> 3;
    const uint32_t b_lane_row = (uint32_t)((bj >> 1) * 8 + (lane & 7));
    const uint32_t b_lane_k   = (uint32_t)((bj & 1) * 16);
    const int erow = lane >> 2;
    const int ecol = (lane & 3) * 2;

    while (true) {
        if (tid == 0) s_t = atomicAdd(&g_tile_ctr, 1);
        __syncthreads();
        const int u = s_t;
        if (u >= ntiles) break;
        const int ks = u & (KSPLIT - 1);
        const int t  = u >> 2;
        const int m0 = (t >> 3) * BM;      // H1P/BN = 8 n-tiles
        const int n0 = (t & 7) * BN;

        const __nv_bfloat16* Abase = g_Xbf + (size_t)m0 * KDIM + (size_t)ks * KT_PER * BK;
        const __nv_bfloat16* Bbase = g_W1t + (size_t)n0 * KDIM + (size_t)ks * KT_PER * BK;

        float acc[4][4][4];
#pragma unroll
        for (int i = 0; i < 4; i++)
#pragma unroll
            for (int j = 0; j < 4; j++)
#pragma unroll
                for (int r = 0; r < 4; r++) acc[i][j][r] = 0.0f;

        auto load_stage = [&](int kt, int stage) {
            uint32_t as = sb + stage * STAGE_B;
            uint32_t bs = as + A_TILE_B;
            const __nv_bfloat16* asrc = Abase + (size_t)kt * BK + lc * 8;
            const __nv_bfloat16* bsrc = Bbase + (size_t)kt * BK + lc * 8;
#pragma unroll
            for (int i = 0; i < 2; i++) {
                int r = lr + 64 * i;
                cpa16(as + r * (RSTRIDE * 2) + lc * 16, asrc + (size_t)r * KDIM);
                cpa16(bs + r * (RSTRIDE * 2) + lc * 16, bsrc + (size_t)r * KDIM);
            }
        };

#pragma unroll
        for (int s = 0; s < STAGES - 1; s++) {
            load_stage(s, s);
            asm volatile("cp.async.commit_group;\n" ::);
        }

        for (int kt = 0; kt < KT_PER; kt++) {
            asm volatile("cp.async.wait_group %0;\n" :: "n"(STAGES - 2));
            __syncthreads();
            if (kt + STAGES - 1 < KT_PER)
                load_stage(kt + STAGES - 1, (kt + STAGES - 1) & (STAGES - 1));
            asm volatile("cp.async.commit_group;\n" ::);

            const uint32_t as = sb + (kt & (STAGES - 1)) * STAGE_B;
            const uint32_t bs = as + A_TILE_B;

#pragma unroll
            for (int kss = 0; kss < 2; kss++) {
                uint32_t af[4][4];
#pragma unroll
                for (int ms = 0; ms < 4; ms++) {
                    uint32_t row = (uint32_t)(warp_m * 64 + ms * 16) + a_lane_row;
                    ldsm4(af[ms][0], af[ms][1], af[ms][2], af[ms][3],
                          as + row * (RSTRIDE * 2) + kss * 32 + a_lane_k);
                }
                uint32_t bf[4][2];
#pragma unroll
                for (int np = 0; np < 2; np++) {
                    uint32_t row = (uint32_t)(warp_n * 32 + np * 16) + b_lane_row;
                    ldsm4(bf[2 * np][0], bf[2 * np][1], bf[2 * np + 1][0], bf[2 * np + 1][1],
                          bs + row * (RSTRIDE * 2) + kss * 32 + b_lane_k);
                }
#pragma unroll
                for (int ms = 0; ms < 4; ms++)
#pragma unroll
                    for (int nf = 0; nf < 4; nf++)
                        mma_bf16(acc[ms][nf], af[ms], bf[nf]);
            }
        }

        // epilogue: raw partials -> g_psum[ks] (full 1024-wide, no predicates)
        float* pbase = g_psum + (size_t)ks * MROWS * H1P;
#pragma unroll
        for (int ms = 0; ms < 4; ms++) {
            int r0 = m0 + warp_m * 64 + ms * 16 + erow;
#pragma unroll
            for (int nf = 0; nf < 4; nf++) {
                int col = n0 + warp_n * 32 + nf * 8 + ecol;
                *(float2*)(pbase + (size_t)r0 * H1P + col) =
                    make_float2(acc[ms][nf][0], acc[ms][nf][1]);
                *(float2*)(pbase + (size_t)(r0 + 8) * H1P + col) =
                    make_float2(acc[ms][nf][2], acc[ms][nf][3]);
            }
        }
        asm volatile("cp.async.wait_group 0;\n" ::);
        __syncthreads();
    }
}

// ============================================================================
// head: GEMM2 k-split; reads psum slices directly (+bias+relu fused)
// grid (64, 5), block 128 (1 row/thread)
// ============================================================================
__global__ void head_partial_kernel(const float* __restrict__ W2,
                                    const float* __restrict__ b1) {
    if (blockIdx.x >= g_mtiles) return;
    __shared__ float hs[128][41];
    __shared__ float w2s[40 * 40];
    __shared__ float bls[40];
    const int tid = threadIdx.x;
    const int row0 = blockIdx.x * 128;
    const int kc0 = blockIdx.y * 5;

    const float* ps0 = g_psum + 0 * (size_t)MROWS * H1P;
    const float* ps1 = g_psum + 1 * (size_t)MROWS * H1P;
    const float* ps2 = g_psum + 2 * (size_t)MROWS * H1P;
    const float* ps3 = g_psum + 3 * (size_t)MROWS * H1P;

    float acc[H2];
#pragma unroll
    for (int c = 0; c < H2; c++) acc[c] = 0.0f;

    for (int kc = kc0; kc < kc0 + 5; kc++) {
        if (tid < 40) bls[tid] = b1[kc * 40 + tid];
#pragma unroll 8
        for (int i = 0; i < 40; i++) {
            int idx = tid + 128 * i;
            int r = idx / 40, k = idx - r * 40;
            size_t off = (size_t)(row0 + r) * H1P + kc * 40 + k;
            hs[r][k] = ps0[off] + ps1[off] + ps2[off] + ps3[off];
        }
        __syncthreads();
#pragma unroll 8
        for (int i = 0; i < 40; i++) {
            int idx = tid + 128 * i;
            int r = idx / 40, k = idx - r * 40;
            hs[r][k] = fmaxf(hs[r][k] + bls[k], 0.0f);
        }
#pragma unroll
        for (int i = 0; i < 13; i++) {
            int idx = tid + 128 * i;
            if (idx < 1600) w2s[idx] = W2[kc * 40 * H2 + idx];
        }
        __syncthreads();
#pragma unroll 5
        for (int k = 0; k < 40; k++) {
            float a = hs[tid][k];
            const float4* wr = (const float4*)(w2s + k * H2);
#pragma unroll
            for (int c4 = 0; c4 < 10; c4++) {
                float4 w = wr[c4];
                acc[c4 * 4 + 0] += a * w.x;
                acc[c4 * 4 + 1] += a * w.y;
                acc[c4 * 4 + 2] += a * w.z;
                acc[c4 * 4 + 3] += a * w.w;
            }
        }
        __syncthreads();
    }
    float4* dst = (float4*)&g_part[blockIdx.y][(row0 + tid) * H2];
#pragma unroll
    for (int c4 = 0; c4 < 10; c4++)
        dst[c4] = make_float4(acc[c4 * 4], acc[c4 * 4 + 1], acc[c4 * 4 + 2], acc[c4 * 4 + 3]);
}

__global__ void head_combine_kernel(const float* __restrict__ b2,
                                    const float* __restrict__ W3,
                                    const float* __restrict__ b3) {
    int row = blockIdx.x * blockDim.x + threadIdx.x;
    if (row >= g_mtiles * 128) return;
    float4 a[10];
    const float4* p0 = (const float4*)&g_part[0][row * H2];
#pragma unroll
    for (int i = 0; i < 10; i++) a[i] = p0[i];
#pragma unroll
    for (int p = 1; p < 5; p++) {
        const float4* pp = (const float4*)&g_part[p][row * H2];
#pragma unroll
        for (int i = 0; i < 10; i++) {
            float4 v = pp[i];
            a[i].x += v.x; a[i].y += v.y; a[i].z += v.z; a[i].w += v.w;
        }
    }
    float logit = b3[0];
#pragma unroll
    for (int i = 0; i < 10; i++) {
        float4 bb = *(const float4*)(b2 + i * 4);
        float4 ww = *(const float4*)(W3 + i * 4);
        logit += fmaxf(a[i].x + bb.x, 0.0f) * ww.x;
        logit += fmaxf(a[i].y + bb.y, 0.0f) * ww.y;
        logit += fmaxf(a[i].z + bb.z, 0.0f) * ww.z;
        logit += fmaxf(a[i].w + bb.w, 0.0f) * ww.w;
    }
    g_logits[row] = 1.0f / (1.0f + expf(-logit));
}

// ============================================================================
// masked gather through the inverse map
// ============================================================================
__global__ void gather_kernel(const void* __restrict__ tsp, float* __restrict__ out) {
    int i = blockIdx.x * blockDim.x + threadIdx.x;
    if (i >= MROWS) return;
    long long ts = g_ts_is_i32 ? (long long)((const int*)tsp)[i]
                               : ((const long long*)tsp)[i];
    float r = 0.0f;
    if (ts != 0) {
        int pos = ((i >> 9) << 9) + (int)ts;
        r = g_logits[g_cidx[pos]];
    }
    out[i] = r;
}

// ============================================================================
// launch
// ============================================================================
extern "C" void kernel_launch(void* const* d_in, const int* in_sizes, int n_in,
                              void* d_out, int out_size) {
    const float* X   = (const float*)d_in[0];
    const void*  tsp = d_in[1];
    const float* W1  = (const float*)d_in[2];
    const float* b1  = (const float*)d_in[3];
    const float* W2  = (const float*)d_in[4];
    const float* b2  = (const float*)d_in[5];
    const float* W3  = (const float*)d_in[6];
    const float* b3  = (const float*)d_in[7];
    float* out = (float*)d_out;
    (void)in_sizes; (void)n_in; (void)out_size;

    cudaFuncSetAttribute(gemm1_kernel,
                         cudaFuncAttributeMaxDynamicSharedMemorySize, SMEM_B);

    prep_all_kernel<<<1, 1024>>>(tsp);

    convert_x_rows_kernel<<<1024, 256>>>(X);
    convert_w1_kernel<<<dim3(KDIM / 32, H1P / 32), dim3(32, 8)>>>(W1);

    gemm1_kernel<<<296, 256, SMEM_B>>>();

    head_partial_kernel<<<dim3(64, 5), 128>>>(W2, b1);
    head_combine_kernel<<<32, 256>>>(b2, W3, b3);
    gather_kernel<<<32, 256>>>(tsp, out);
}

// round 17
// speedup vs baseline: 1.0365x; 1.0293x over previous
#include <cuda_runtime.h>
#include <cuda_bf16.h>
#include <cstdint>
#include <math.h>

// ---------------- problem dims ----------------
#define MROWS 8192
#define KDIM  9984
#define H1    1000
#define H1P   1024
#define H2    40

// ---------------- GEMM1 tiling ----------------
#define BM 128
#define BN 128
#define BK 32
#define STAGES 4
#define NKT (KDIM / BK)          // 312
#define KSPLIT 6
#define KT_PER (NKT / KSPLIT)    // 52
#define RSTRIDE 40               // bf16 elems per smem row (80 B) -> conflict-free ldmatrix
#define A_TILE_B (BM * RSTRIDE * 2)          // 10240
#define STAGE_B  ((BM + BN) * RSTRIDE * 2)   // 20480
#define SMEM_B   (STAGES * STAGE_B)          // 81920

// ---------------- scratch (device globals; no runtime alloc) ----------------
__device__ __nv_bfloat16 g_Xbf[(size_t)MROWS * KDIM];   // compact bf16 X rows
__device__ __nv_bfloat16 g_W1t[(size_t)H1P * KDIM];     // [n][k], rows >= 1000 zero
__device__ float g_psum[(size_t)KSPLIT * MROWS * H1P];  // split-K partials
__device__ float g_h1[(size_t)MROWS * H1];              // compact, post bias+relu
__device__ float g_part[25][MROWS * H2];                // head kc partials
__device__ float g_logits[MROWS];                       // compact
__device__ int   g_ts_is_i32;
__device__ int   g_cidx[MROWS];                         // (b,s) -> compact row
__device__ int   g_list[MROWS];                         // compact row -> original row
__device__ int   g_count, g_mtiles, g_ntiles, g_tile_ctr;

// ============================================================================
// helpers
// ============================================================================
__device__ __forceinline__ uint32_t smem_u32(const void* p) {
    uint32_t a;
    asm("{ .reg .u64 t; cvta.to.shared.u64 t, %1; cvt.u32.u64 %0, t; }"
        : "=r"(a) : "l"(p));
    return a;
}
__device__ __forceinline__ void cpa16(uint32_t dst, const void* src) {
    asm volatile("cp.async.cg.shared.global [%0], [%1], 16;\n" :: "r"(dst), "l"(src));
}
__device__ __forceinline__ void ldsm4(uint32_t& r0, uint32_t& r1, uint32_t& r2,
                                      uint32_t& r3, uint32_t addr) {
    asm volatile("ldmatrix.sync.aligned.m8n8.x4.shared.b16 {%0,%1,%2,%3}, [%4];"
                 : "=r"(r0), "=r"(r1), "=r"(r2), "=r"(r3) : "r"(addr));
}
__device__ __forceinline__ void mma_bf16(float* d, const uint32_t* a, const uint32_t* b) {
    asm volatile(
        "mma.sync.aligned.m16n8k16.row.col.f32.bf16.bf16.f32 "
        "{%0,%1,%2,%3}, {%4,%5,%6,%7}, {%8,%9}, {%0,%1,%2,%3};\n"
        : "+f"(d[0]), "+f"(d[1]), "+f"(d[2]), "+f"(d[3])
        : "r"(a[0]), "r"(a[1]), "r"(a[2]), "r"(a[3]), "r"(b[0]), "r"(b[1]));
}

// ============================================================================
// merged prep: detect dtype, mark (in smem), scan, compact -- ONE block
// ============================================================================
__global__ void prep_all_kernel(const void* __restrict__ tsp) {
    __shared__ unsigned char mark[MROWS];    // 8 KB
    __shared__ int wsum[32];
    __shared__ int s_is32;
    const int tid = threadIdx.x, lane = tid & 31, wid = tid >> 5;

    if (tid == 0) s_is32 = 0;
    __syncthreads();
    {
        const unsigned int* w = (const unsigned int*)tsp;
        int loc = 0;
#pragma unroll
        for (int j = 0; j < 4; j++)
            if (w[2 * (tid + 1024 * j) + 1] != 0u) loc = 1;
        if (loc) s_is32 = 1;
    }
    ((unsigned long long*)mark)[tid] = 0ULL;
    __syncthreads();
    const int is32 = s_is32;

#pragma unroll
    for (int j = 0; j < 8; j++) {
        int i = tid + 1024 * j;
        long long ts = is32 ? (long long)((const int*)tsp)[i]
                            : ((const long long*)tsp)[i];
        if (ts != 0) mark[((i >> 9) << 9) + (int)ts] = 1;
    }
    __syncthreads();

    const int base = tid * 8;
    unsigned long long m = ((const unsigned long long*)mark)[tid];
    int bit[8], loc8[8], s = 0;
#pragma unroll
    for (int j = 0; j < 8; j++) {
        bit[j] = (int)((m >> (8 * j)) & 1ULL);
        loc8[j] = s;
        s += bit[j];
    }
    int v = s;
#pragma unroll
    for (int o = 1; o < 32; o <<= 1) {
        int u = __shfl_up_sync(0xffffffffu, v, o);
        if (lane >= o) v += u;
    }
    if (lane == 31) wsum[wid] = v;
    __syncthreads();
    if (wid == 0) {
        int w = wsum[lane];
#pragma unroll
        for (int o = 1; o < 32; o <<= 1) {
            int u = __shfl_up_sync(0xffffffffu, w, o);
            if (lane >= o) w += u;
        }
        wsum[lane] = w;
    }
    __syncthreads();
    int tb = (wid > 0 ? wsum[wid - 1] : 0) + (v - s);
#pragma unroll
    for (int j = 0; j < 8; j++) {
        if (bit[j]) {
            int c = tb + loc8[j];
            g_cidx[base + j] = c;
            g_list[c] = base + j;
        }
    }
    const int total = wsum[31];
    const int mt = (total + 127) >> 7;
    if (tid == 0) {
        g_count = total;
        g_mtiles = mt;
        g_ntiles = mt * (H1P / BN) * KSPLIT;
        g_tile_ctr = 0;
        g_ts_is_i32 = is32;
    }
    for (int i = total + tid; i < mt * 128; i += 1024) g_list[i] = 0;  // pad
}

// ============================================================================
// pre-pass: convert only needed X rows fp32 -> bf16 (compact layout)
// ============================================================================
__global__ void convert_x_rows_kernel(const float* __restrict__ X) {
    const int padded = g_mtiles * 128;
    for (int r = blockIdx.x; r < padded; r += gridDim.x) {
        int row = g_list[r];
        const float4* src = (const float4*)(X + (size_t)row * KDIM);
        uint4* dst = (uint4*)(g_Xbf + (size_t)r * KDIM);
        for (int c = threadIdx.x; c < KDIM / 8; c += blockDim.x) {
            float4 v0 = src[2 * c], v1 = src[2 * c + 1];
            __nv_bfloat162 p0 = __floats2bfloat162_rn(v0.x, v0.y);
            __nv_bfloat162 p1 = __floats2bfloat162_rn(v0.z, v0.w);
            __nv_bfloat162 p2 = __floats2bfloat162_rn(v1.x, v1.y);
            __nv_bfloat162 p3 = __floats2bfloat162_rn(v1.z, v1.w);
            uint4 o;
            o.x = *(uint32_t*)&p0; o.y = *(uint32_t*)&p1;
            o.z = *(uint32_t*)&p2; o.w = *(uint32_t*)&p3;
            dst[c] = o;
        }
    }
}

// W1[K][H1] fp32 -> g_W1t[H1P][K] bf16 (transpose + pad)
__global__ void convert_w1_kernel(const float* __restrict__ W1) {
    __shared__ float t[32][33];
    int k0 = blockIdx.x * 32, n0 = blockIdx.y * 32;
#pragma unroll
    for (int yy = 0; yy < 32; yy += 8) {
        int k = k0 + threadIdx.y + yy, n = n0 + threadIdx.x;
        t[threadIdx.y + yy][threadIdx.x] = (n < H1) ? W1[(size_t)k * H1 + n] : 0.0f;
    }
    __syncthreads();
#pragma unroll
    for (int yy = 0; yy < 32; yy += 8) {
        int n = n0 + threadIdx.y + yy, k = k0 + threadIdx.x;
        g_W1t[(size_t)n * KDIM + k] = __float2bfloat16(t[threadIdx.x][threadIdx.y + yy]);
    }
}

// ============================================================================
// GEMM1 (persistent, work-stealing, split-K=6): partials into g_psum
// BM=128 BN=128 BK=32, 8 warps (2m x 4n), warp tile 64x32, 2 CTAs/SM
// ============================================================================
__global__ void __launch_bounds__(256, 2)
gemm1_kernel() {
    extern __shared__ __align__(128) char smem[];
    const uint32_t sb = smem_u32(smem);
    __shared__ int s_t;

    const int tid = threadIdx.x;
    const int warp = tid >> 5;
    const int lane = tid & 31;
    const int warp_m = warp & 1;     // 0..1, 64 rows
    const int warp_n = warp >> 1;    // 0..3, 32 cols
    const int ntiles = g_ntiles;

    const int lr = tid >> 2;         // 0..63
    const int lc = tid & 3;          // 0..3
    const uint32_t a_lane_row = (uint32_t)(lane & 15);
    const uint32_t a_lane_k   = (uint32_t)((lane >> 4) * 16);
    const int bj = lane >> 3;
    const uint32_t b_lane_row = (uint32_t)((bj >> 1) * 8 + (lane & 7));
    const uint32_t b_lane_k   = (uint32_t)((bj & 1) * 16);
    const int erow = lane >> 2;
    const int ecol = (lane & 3) * 2;

    while (true) {
        if (tid == 0) s_t = atomicAdd(&g_tile_ctr, 1);
        __syncthreads();
        const int u = s_t;
        if (u >= ntiles) break;
        const int ks = u % KSPLIT;
        const int t  = u / KSPLIT;
        const int m0 = (t >> 3) * BM;      // H1P/BN = 8 n-tiles
        const int n0 = (t & 7) * BN;

        const __nv_bfloat16* Abase = g_Xbf + (size_t)m0 * KDIM + (size_t)ks * KT_PER * BK;
        const __nv_bfloat16* Bbase = g_W1t + (size_t)n0 * KDIM + (size_t)ks * KT_PER * BK;

        float acc[4][4][4];
#pragma unroll
        for (int i = 0; i < 4; i++)
#pragma unroll
            for (int j = 0; j < 4; j++)
#pragma unroll
                for (int r = 0; r < 4; r++) acc[i][j][r] = 0.0f;

        auto load_stage = [&](int kt, int stage) {
            uint32_t as = sb + stage * STAGE_B;
            uint32_t bs = as + A_TILE_B;
            const __nv_bfloat16* asrc = Abase + (size_t)kt * BK + lc * 8;
            const __nv_bfloat16* bsrc = Bbase + (size_t)kt * BK + lc * 8;
#pragma unroll
            for (int i = 0; i < 2; i++) {
                int r = lr + 64 * i;
                cpa16(as + r * (RSTRIDE * 2) + lc * 16, asrc + (size_t)r * KDIM);
                cpa16(bs + r * (RSTRIDE * 2) + lc * 16, bsrc + (size_t)r * KDIM);
            }
        };

#pragma unroll
        for (int s = 0; s < STAGES - 1; s++) {
            load_stage(s, s);
            asm volatile("cp.async.commit_group;\n" ::);
        }

        for (int kt = 0; kt < KT_PER; kt++) {
            asm volatile("cp.async.wait_group %0;\n" :: "n"(STAGES - 2));
            __syncthreads();
            if (kt + STAGES - 1 < KT_PER)
                load_stage(kt + STAGES - 1, (kt + STAGES - 1) & (STAGES - 1));
            asm volatile("cp.async.commit_group;\n" ::);

            const uint32_t as = sb + (kt & (STAGES - 1)) * STAGE_B;
            const uint32_t bs = as + A_TILE_B;

#pragma unroll
            for (int kss = 0; kss < 2; kss++) {
                uint32_t af[4][4];
#pragma unroll
                for (int ms = 0; ms < 4; ms++) {
                    uint32_t row = (uint32_t)(warp_m * 64 + ms * 16) + a_lane_row;
                    ldsm4(af[ms][0], af[ms][1], af[ms][2], af[ms][3],
                          as + row * (RSTRIDE * 2) + kss * 32 + a_lane_k);
                }
                uint32_t bf[4][2];
#pragma unroll
                for (int np = 0; np < 2; np++) {
                    uint32_t row = (uint32_t)(warp_n * 32 + np * 16) + b_lane_row;
                    ldsm4(bf[2 * np][0], bf[2 * np][1], bf[2 * np + 1][0], bf[2 * np + 1][1],
                          bs + row * (RSTRIDE * 2) + kss * 32 + b_lane_k);
                }
#pragma unroll
                for (int ms = 0; ms < 4; ms++)
#pragma unroll
                    for (int nf = 0; nf < 4; nf++)
                        mma_bf16(acc[ms][nf], af[ms], bf[nf]);
            }
        }

        // epilogue: raw partials -> g_psum[ks] (full 1024-wide, no predicates)
        float* pbase = g_psum + (size_t)ks * MROWS * H1P;
#pragma unroll
        for (int ms = 0; ms < 4; ms++) {
            int r0 = m0 + warp_m * 64 + ms * 16 + erow;
#pragma unroll
            for (int nf = 0; nf < 4; nf++) {
                int col = n0 + warp_n * 32 + nf * 8 + ecol;
                *(float2*)(pbase + (size_t)r0 * H1P + col) =
                    make_float2(acc[ms][nf][0], acc[ms][nf][1]);
                *(float2*)(pbase + (size_t)(r0 + 8) * H1P + col) =
                    make_float2(acc[ms][nf][2], acc[ms][nf][3]);
            }
        }
        asm volatile("cp.async.wait_group 0;\n" ::);
        __syncthreads();
    }
}

// ============================================================================
// combine split-K partials + bias + relu -> g_h1 (streaming, coalesced)
// ============================================================================
__global__ void h1_combine_kernel(const float* __restrict__ b1) {
    const int padded = g_mtiles * 128;
    for (int r = blockIdx.x; r < padded; r += gridDim.x) {
        const float4* p0 = (const float4*)(g_psum + 0 * (size_t)MROWS * H1P + (size_t)r * H1P);
        const float4* p1 = (const float4*)(g_psum + 1 * (size_t)MROWS * H1P + (size_t)r * H1P);
        const float4* p2 = (const float4*)(g_psum + 2 * (size_t)MROWS * H1P + (size_t)r * H1P);
        const float4* p3 = (const float4*)(g_psum + 3 * (size_t)MROWS * H1P + (size_t)r * H1P);
        const float4* p4 = (const float4*)(g_psum + 4 * (size_t)MROWS * H1P + (size_t)r * H1P);
        const float4* p5 = (const float4*)(g_psum + 5 * (size_t)MROWS * H1P + (size_t)r * H1P);
        float4* dst = (float4*)(g_h1 + (size_t)r * H1);
        for (int c = threadIdx.x; c < H1 / 4; c += blockDim.x) {
            float4 a = p0[c], b = p1[c], d = p2[c], e = p3[c], f = p4[c], g = p5[c];
            float4 bb = *(const float4*)(b1 + 4 * c);
            float4 o;
            o.x = fmaxf(a.x + b.x + d.x + e.x + f.x + g.x + bb.x, 0.0f);
            o.y = fmaxf(a.y + b.y + d.y + e.y + f.y + g.y + bb.y, 0.0f);
            o.z = fmaxf(a.z + b.z + d.z + e.z + f.z + g.z + bb.z, 0.0f);
            o.w = fmaxf(a.w + b.w + d.w + e.w + f.w + g.w + bb.w, 0.0f);
            dst[c] = o;
        }
    }
}

// ============================================================================
// head: GEMM2 one 40-col kc chunk per block -> g_part[kc]
// grid (64, 25), block 128 (1 row/thread)
// ============================================================================
__global__ void head_partial_kernel(const float* __restrict__ W2) {
    if (blockIdx.x >= g_mtiles) return;
    __shared__ float hs[128][41];
    __shared__ float w2s[40 * 40];
    const int tid = threadIdx.x;
    const int row0 = blockIdx.x * 128;
    const int kc = blockIdx.y;

#pragma unroll 8
    for (int i = 0; i < 40; i++) {
        int idx = tid + 128 * i;
        int r = idx / 40, k = idx - r * 40;
        hs[r][k] = g_h1[(size_t)(row0 + r) * H1 + kc * 40 + k];
    }
#pragma unroll
    for (int i = 0; i < 13; i++) {
        int idx = tid + 128 * i;
        if (idx < 1600) w2s[idx] = W2[kc * 40 * H2 + idx];
    }
    __syncthreads();

    float acc[H2];
#pragma unroll
    for (int c = 0; c < H2; c++) acc[c] = 0.0f;
#pragma unroll 5
    for (int k = 0; k < 40; k++) {
        float a = hs[tid][k];
        const float4* wr = (const float4*)(w2s + k * H2);
#pragma unroll
        for (int c4 = 0; c4 < 10; c4++) {
            float4 w = wr[c4];
            acc[c4 * 4 + 0] += a * w.x;
            acc[c4 * 4 + 1] += a * w.y;
            acc[c4 * 4 + 2] += a * w.z;
            acc[c4 * 4 + 3] += a * w.w;
        }
    }
    float4* dst = (float4*)&g_part[kc][(row0 + tid) * H2];
#pragma unroll
    for (int c4 = 0; c4 < 10; c4++)
        dst[c4] = make_float4(acc[c4 * 4], acc[c4 * 4 + 1], acc[c4 * 4 + 2], acc[c4 * 4 + 3]);
}

__global__ void head_combine_kernel(const float* __restrict__ b2,
                                    const float* __restrict__ W3,
                                    const float* __restrict__ b3) {
    int row = blockIdx.x * blockDim.x + threadIdx.x;
    if (row >= g_mtiles * 128) return;
    float4 a[10];
    const float4* p0 = (const float4*)&g_part[0][row * H2];
#pragma unroll
    for (int i = 0; i < 10; i++) a[i] = p0[i];
    for (int p = 1; p < 25; p++) {
        const float4* pp = (const float4*)&g_part[p][row * H2];
#pragma unroll
        for (int i = 0; i < 10; i++) {
            float4 v = pp[i];
            a[i].x += v.x; a[i].y += v.y; a[i].z += v.z; a[i].w += v.w;
        }
    }
    float logit = b3[0];
#pragma unroll
    for (int i = 0; i < 10; i++) {
        float4 bb = *(const float4*)(b2 + i * 4);
        float4 ww = *(const float4*)(W3 + i * 4);
        logit += fmaxf(a[i].x + bb.x, 0.0f) * ww.x;
        logit += fmaxf(a[i].y + bb.y, 0.0f) * ww.y;
        logit += fmaxf(a[i].z + bb.z, 0.0f) * ww.z;
        logit += fmaxf(a[i].w + bb.w, 0.0f) * ww.w;
    }
    g_logits[row] = 1.0f / (1.0f + expf(-logit));
}

// ============================================================================
// masked gather through the inverse map
// ============================================================================
__global__ void gather_kernel(const void* __restrict__ tsp, float* __restrict__ out) {
    int i = blockIdx.x * blockDim.x + threadIdx.x;
    if (i >= MROWS) return;
    long long ts = g_ts_is_i32 ? (long long)((const int*)tsp)[i]
                               : ((const long long*)tsp)[i];
    float r = 0.0f;
    if (ts != 0) {
        int pos = ((i >> 9) << 9) + (int)ts;
        r = g_logits[g_cidx[pos]];
    }
    out[i] = r;
}

// ============================================================================
// launch
// ============================================================================
extern "C" void kernel_launch(void* const* d_in, const int* in_sizes, int n_in,
                              void* d_out, int out_size) {
    const float* X   = (const float*)d_in[0];
    const void*  tsp = d_in[1];
    const float* W1  = (const float*)d_in[2];
    const float* b1  = (const float*)d_in[3];
    const float* W2  = (const float*)d_in[4];
    const float* b2  = (const float*)d_in[5];
    const float* W3  = (const float*)d_in[6];
    const float* b3  = (const float*)d_in[7];
    float* out = (float*)d_out;
    (void)in_sizes; (void)n_in; (void)out_size;

    cudaFuncSetAttribute(gemm1_kernel,
                         cudaFuncAttributeMaxDynamicSharedMemorySize, SMEM_B);

    prep_all_kernel<<<1, 1024>>>(tsp);

    convert_x_rows_kernel<<<1024, 256>>>(X);
    convert_w1_kernel<<<dim3(KDIM / 32, H1P / 32), dim3(32, 8)>>>(W1);

    gemm1_kernel<<<296, 256, SMEM_B>>>();
    h1_combine_kernel<<<512, 256>>>(b1);

    head_partial_kernel<<<dim3(64, 25), 128>>>(W2);
    head_combine_kernel<<<32, 256>>>(b2, W3, b3);
    gather_kernel<<<32, 256>>>(tsp, out);
}